// round 1
// baseline (speedup 1.0000x reference)
#include <cuda_runtime.h>
#include <cuda_bf16.h>
#include <math.h>

#define H_DIM 180
#define W_DIM 360
#define NPIX  (H_DIM * W_DIM)       // 64800
#define C_DIM 256
#define M_OUT (2 * C_DIM)           // 512
#define K_DIM C_DIM                 // 256

// Scratch for vel = W @ X + b  : [512, 64800] fp32 (132.7 MB)
__device__ float g_vel[(size_t)M_OUT * NPIX];

// ---------------------------------------------------------------------------
// Kernel 1: vel[o, p] = sum_c w_vel[o, c] * hidden[c, p] + b_vel[o]
// Classic 128x128x8 smem-tiled fp32 GEMM, 256 threads, 8x8 register tile.
// A = w_vel [512 x 256] row-major (k contiguous)
// B = hidden [256 x 64800] row-major (pixel contiguous)
// ---------------------------------------------------------------------------
__global__ __launch_bounds__(256) void gemm_vel_kernel(
    const float* __restrict__ Wm,     // [512,256]
    const float* __restrict__ Xm,     // [256, 64800]
    const float* __restrict__ bias)   // [512]
{
    __shared__ float As[8][128];   // As[k][m]
    __shared__ float Bs[8][128];   // Bs[k][n]

    const int tid = threadIdx.x;
    const int tx  = tid & 15;      // 0..15 (n direction)
    const int ty  = tid >> 4;      // 0..15 (m direction)
    const int n0  = blockIdx.x * 128;
    const int m0  = blockIdx.y * 128;

    // global->smem load assignments
    const int arow  = tid >> 1;          // 0..127 (m within tile)
    const int akcol = (tid & 1) << 2;    // 0 or 4 (k within tile)
    const int brow  = tid >> 5;          // 0..7   (k within tile)
    const int bcol  = (tid & 31) << 2;   // 0..124 (n within tile)
    // NPIX % 4 == 0 and bcol % 4 == 0 -> float4 is all-in or all-out
    const bool bvalid = (n0 + bcol) < NPIX;

    float acc[8][8];
    #pragma unroll
    for (int i = 0; i < 8; i++)
        #pragma unroll
        for (int j = 0; j < 8; j++)
            acc[i][j] = 0.0f;

    const float* Ap = Wm + (size_t)(m0 + arow) * K_DIM + akcol;
    const float* Xp = Xm + (size_t)brow * NPIX + n0 + bcol;

    for (int k0 = 0; k0 < K_DIM; k0 += 8) {
        float4 av = *reinterpret_cast<const float4*>(Ap + k0);
        float4 bv = make_float4(0.f, 0.f, 0.f, 0.f);
        if (bvalid) bv = *reinterpret_cast<const float4*>(Xp + (size_t)k0 * NPIX);

        __syncthreads();   // previous tile fully consumed
        As[akcol + 0][arow] = av.x;
        As[akcol + 1][arow] = av.y;
        As[akcol + 2][arow] = av.z;
        As[akcol + 3][arow] = av.w;
        *reinterpret_cast<float4*>(&Bs[brow][bcol]) = bv;
        __syncthreads();

        #pragma unroll
        for (int k = 0; k < 8; k++) {
            float a[8], b[8];
            *reinterpret_cast<float4*>(&a[0]) = *reinterpret_cast<const float4*>(&As[k][ty * 4]);
            *reinterpret_cast<float4*>(&a[4]) = *reinterpret_cast<const float4*>(&As[k][64 + ty * 4]);
            *reinterpret_cast<float4*>(&b[0]) = *reinterpret_cast<const float4*>(&Bs[k][tx * 4]);
            *reinterpret_cast<float4*>(&b[4]) = *reinterpret_cast<const float4*>(&Bs[k][64 + tx * 4]);
            #pragma unroll
            for (int i = 0; i < 8; i++)
                #pragma unroll
                for (int j = 0; j < 8; j++)
                    acc[i][j] = fmaf(a[i], b[j], acc[i][j]);
        }
    }

    #pragma unroll
    for (int i = 0; i < 8; i++) {
        const int m = m0 + ((i < 4) ? (ty * 4 + i) : (64 + ty * 4 + i - 4));
        const float bb = bias[m];
        float* dst = &g_vel[(size_t)m * NPIX];
        const int n1 = n0 + tx * 4;
        if (n1 < NPIX) {
            float4 o = make_float4(acc[i][0] + bb, acc[i][1] + bb,
                                   acc[i][2] + bb, acc[i][3] + bb);
            *reinterpret_cast<float4*>(dst + n1) = o;
        }
        const int n2 = n0 + 64 + tx * 4;
        if (n2 < NPIX) {
            float4 o = make_float4(acc[i][4] + bb, acc[i][5] + bb,
                                   acc[i][6] + bb, acc[i][7] + bb);
            *reinterpret_cast<float4*>(dst + n2) = o;
        }
    }
}

// ---------------------------------------------------------------------------
// Kernel 2: departure point + bicubic sample with geo-cyclic pad folded
// into index math. One thread per (channel, pixel).
// ---------------------------------------------------------------------------
__device__ __forceinline__ float cc1f(float x) {
    // ((A+2)x - (A+3)) x^2 + 1,  A = -0.75
    return (1.25f * x - 2.25f) * x * x + 1.0f;
}
__device__ __forceinline__ float cc2f(float x) {
    // ((A x - 5A) x + 8A) x - 4A,  A = -0.75
    return ((-0.75f * x + 3.75f) * x - 6.0f) * x + 3.0f;
}

__global__ __launch_bounds__(256) void sample_kernel(
    const float* __restrict__ hf,     // [256, 180, 360]
    const float* __restrict__ latg,   // [64800]
    const float* __restrict__ lng,    // [64800]
    const void*  __restrict__ dtp,    // scalar (int32 or fp32)
    float* __restrict__ out)          // [256, 64800]
{
    const int p = blockIdx.x * 256 + threadIdx.x;
    const int c = blockIdx.y;
    if (p >= NPIX) return;

    // dt: robust to int32 vs float32 encoding of the scalar
    const int ib = *reinterpret_cast<const int*>(dtp);
    const float dtf = (ib > -1000000 && ib < 1000000) ? (float)ib : __int_as_float(ib);

    const float u = g_vel[(size_t)c * NPIX + p];
    const float v = g_vel[(size_t)(c + C_DIM) * NPIX + p];
    const float lat_p = __ldg(&latg[p]);
    const float lon_p = __ldg(&lng[p]);

    const float lon_prime = -u * dtf;
    const float lat_prime = -v * dtf;

    float slp, clp, slo, clo, sla, cla;
    sincosf(lat_prime, &slp, &clp);
    sincosf(lon_prime, &slo, &clo);
    sincosf(lat_p,     &sla, &cla);

    float sin_lat = slp * cla + clp * clo * sla;
    const float lim = 1.0f - 1e-7f;
    sin_lat = fminf(fmaxf(sin_lat, -lim), lim);
    const float lat_dep = asinf(sin_lat);

    const float num = clp * slo;
    const float den = clp * clo * cla - slp * sla;
    const float TWO_PI = 6.28318530717958647692f;
    float lon_dep = lon_p + atan2f(num, den) + TWO_PI;
    lon_dep = fmodf(lon_dep, TWO_PI);
    if (lon_dep < 0.f) lon_dep += TWO_PI;

    const float min_lat = __ldg(&latg[0]);
    const float max_lat = __ldg(&latg[(H_DIM - 1) * W_DIM]);
    const float min_lon = __ldg(&lng[0]);
    const float max_lon = __ldg(&lng[W_DIM - 1]);

    float gx = (2.0f * (lon_dep - min_lon) / (max_lon - min_lon) - 1.0f)
               * ((float)W_DIM / (float)(W_DIM + 2));
    float gy = (2.0f * (lat_dep - min_lat) / (max_lat - min_lat) - 1.0f)
               * ((float)H_DIM / (float)(H_DIM + 2));

    gx = fmodf(gx + 1.0f, 2.0f);
    if (gx < 0.f) gx += 2.0f;
    gx -= 1.0f;
    if (gy < -1.0f) gy = -(2.0f + gy);
    if (gy >  1.0f) gy = 2.0f - gy;

    // padded dims: Hp = 182, Wp = 362
    const float ix = (gx + 1.0f) * 0.5f * 361.0f;
    const float iy = (gy + 1.0f) * 0.5f * 181.0f;
    const float ix0f = floorf(ix);
    const float iy0f = floorf(iy);
    const float fx = ix - ix0f;
    const float fy = iy - iy0f;
    const int ix0 = (int)ix0f;
    const int iy0 = (int)iy0f;

    const float wx0 = cc2f(fx + 1.0f), wx1 = cc1f(fx),
                wx2 = cc1f(1.0f - fx), wx3 = cc2f(2.0f - fx);
    const float wy0 = cc2f(fy + 1.0f), wy1 = cc1f(fy),
                wy2 = cc1f(1.0f - fy), wy3 = cc2f(2.0f - fy);
    const float wxs[4] = {wx0, wx1, wx2, wx3};
    const float wys[4] = {wy0, wy1, wy2, wy3};

    const float* ch = hf + (size_t)c * NPIX;

    float acc = 0.f;
    #pragma unroll
    for (int i = 0; i < 4; i++) {
        int yi = iy0 + i - 1;
        yi = min(max(yi, 0), 181);
        const bool interior = (yi >= 1 && yi <= H_DIM);
        // interior: padded row yi -> orig row yi-1
        // yi==0 (top pad): orig row 0, columns rolled by 180
        // yi==181 (bot pad): orig row H-1, columns rolled by 180
        const int yy = interior ? (yi - 1) : ((yi == 0) ? 0 : (H_DIM - 1));
        const float* rowp = ch + yy * W_DIM;

        float row = 0.f;
        #pragma unroll
        for (int j = 0; j < 4; j++) {
            int xj = ix0 + j - 1;
            xj = min(max(xj, 0), 361);
            int xx;
            if (interior) {
                // padded col 0 -> orig W-1 ; padded col 361 -> orig 0 ; else x-1
                xx = (xj == 0) ? (W_DIM - 1) : ((xj == 361) ? 0 : (xj - 1));
            } else {
                // pole rows: padded[x] = orig_row[(x + 179) mod 360]
                xx = xj + 179;
                if (xx >= W_DIM) xx -= W_DIM;
            }
            row += wxs[j] * __ldg(&rowp[xx]);
        }
        acc += wys[i] * row;
    }

    out[(size_t)c * NPIX + p] = acc;
}

// ---------------------------------------------------------------------------
extern "C" void kernel_launch(void* const* d_in, const int* in_sizes, int n_in,
                              void* d_out, int out_size) {
    const float* hf   = (const float*)d_in[0];   // hidden_features [1,256,180,360]
    const float* latg = (const float*)d_in[1];   // lat_grid  [1,180,360]
    const float* lng  = (const float*)d_in[2];   // lon_grid  [1,180,360]
    const float* wv   = (const float*)d_in[3];   // w_vel [512,256]
    const float* bv   = (const float*)d_in[4];   // b_vel [512]
    const void*  dtp  = d_in[5];                 // dt scalar
    float* out = (float*)d_out;                  // [1,256,180,360] fp32

    dim3 gg((NPIX + 127) / 128, M_OUT / 128);    // 507 x 4
    gemm_vel_kernel<<<gg, 256>>>(wv, hf, bv);

    dim3 gs((NPIX + 255) / 256, C_DIM);          // 254 x 256
    sample_kernel<<<gs, 256>>>(hf, latg, lng, dtp, out);
}

// round 3
// speedup vs baseline: 1.4033x; 1.4033x over previous
#include <cuda_runtime.h>
#include <cuda_bf16.h>
#include <math.h>
#include <cstdint>

#define H_DIM 180
#define W_DIM 360
#define NPIX  64800
#define C_DIM 256
#define M_OUT 512
#define K_DIM 256

// ------------------------- device scratch -----------------------------------
__device__ float         g_vel[(size_t)M_OUT * NPIX];          // 132.7 MB
__device__ __nv_bfloat16 g_xt_hi[(size_t)NPIX * K_DIM];        // 33.2 MB
__device__ __nv_bfloat16 g_xt_lo[(size_t)NPIX * K_DIM];        // 33.2 MB
__device__ __nv_bfloat16 g_w_hi[M_OUT * K_DIM];
__device__ __nv_bfloat16 g_w_lo[M_OUT * K_DIM];

// ------------------------- helpers ------------------------------------------
__device__ __forceinline__ uint32_t smem_u32(const void* p) {
    uint32_t a;
    asm("{ .reg .u64 t; cvta.to.shared.u64 t, %1; cvt.u32.u64 %0, t; }" : "=r"(a) : "l"(p));
    return a;
}
__device__ __forceinline__ void cp16(uint32_t dst, const void* src, int src_bytes) {
    asm volatile("cp.async.cg.shared.global [%0], [%1], 16, %2;"
                 :: "r"(dst), "l"(src), "r"(src_bytes) : "memory");
}
#define CP_COMMIT() asm volatile("cp.async.commit_group;" ::: "memory")
#define CP_WAIT(n)  asm volatile("cp.async.wait_group %0;" :: "n"(n) : "memory")

__device__ __forceinline__ void ldsm_x4(uint32_t (&r)[4], uint32_t addr) {
    asm volatile("ldmatrix.sync.aligned.m8n8.x4.shared.b16 {%0,%1,%2,%3}, [%4];"
                 : "=r"(r[0]), "=r"(r[1]), "=r"(r[2]), "=r"(r[3]) : "r"(addr));
}
__device__ __forceinline__ void mma16816(float (&d)[4], const uint32_t (&a)[4],
                                         uint32_t b0, uint32_t b1) {
    asm volatile("mma.sync.aligned.m16n8k16.row.col.f32.bf16.bf16.f32 "
                 "{%0,%1,%2,%3}, {%4,%5,%6,%7}, {%8,%9}, {%0,%1,%2,%3};"
                 : "+f"(d[0]), "+f"(d[1]), "+f"(d[2]), "+f"(d[3])
                 : "r"(a[0]), "r"(a[1]), "r"(a[2]), "r"(a[3]), "r"(b0), "r"(b1));
}

// ---------------------------------------------------------------------------
// Convert W -> bf16 hi/lo
// ---------------------------------------------------------------------------
__global__ __launch_bounds__(256) void convert_w_kernel(const float* __restrict__ Wm) {
    int i = blockIdx.x * 256 + threadIdx.x;
    if (i < M_OUT * K_DIM) {
        float x = Wm[i];
        __nv_bfloat16 h = __float2bfloat16(x);
        g_w_hi[i] = h;
        g_w_lo[i] = __float2bfloat16(x - __bfloat162float(h));
    }
}

// ---------------------------------------------------------------------------
// Transpose+convert X [256, 64800] fp32 -> XT hi/lo [64800, 256] bf16
// ---------------------------------------------------------------------------
__global__ __launch_bounds__(256) void convert_x_kernel(const float* __restrict__ X) {
    __shared__ float tile[K_DIM][33];
    const int n0   = blockIdx.x * 32;
    const int lane = threadIdx.x & 31;
    const int wrp  = threadIdx.x >> 5;

    #pragma unroll 4
    for (int r = 0; r < 32; r++) {
        int k = r * 8 + wrp;
        tile[k][lane] = X[(size_t)k * NPIX + n0 + lane];
    }
    __syncthreads();

    #pragma unroll
    for (int g = 0; g < 4; g++) {
        int j = wrp * 4 + g;
        size_t p = (size_t)(n0 + j);
        uint32_t hi4[4], lo4[4];
        #pragma unroll
        for (int q = 0; q < 4; q++) {
            float x0 = tile[lane * 8 + q * 2 + 0][j];
            float x1 = tile[lane * 8 + q * 2 + 1][j];
            __nv_bfloat16 h0 = __float2bfloat16(x0);
            __nv_bfloat16 h1 = __float2bfloat16(x1);
            __nv_bfloat16 l0 = __float2bfloat16(x0 - __bfloat162float(h0));
            __nv_bfloat16 l1 = __float2bfloat16(x1 - __bfloat162float(h1));
            hi4[q] = (uint32_t)__bfloat16_as_ushort(h0) | ((uint32_t)__bfloat16_as_ushort(h1) << 16);
            lo4[q] = (uint32_t)__bfloat16_as_ushort(l0) | ((uint32_t)__bfloat16_as_ushort(l1) << 16);
        }
        *reinterpret_cast<uint4*>(&g_xt_hi[p * K_DIM + lane * 8]) = make_uint4(hi4[0], hi4[1], hi4[2], hi4[3]);
        *reinterpret_cast<uint4*>(&g_xt_lo[p * K_DIM + lane * 8]) = make_uint4(lo4[0], lo4[1], lo4[2], lo4[3]);
    }
}

// ---------------------------------------------------------------------------
// HMMA GEMM: g_vel[m,n] = sum_k W[m,k] X[k,n] + bias[m]   (3-term bf16 split)
// CTA tile 128x128, K-chunks of 32 over extended K = 3 x 256.
// 8 warps (4m x 2n), warp tile 32x64, mma.m16n8k16 bf16, cp.async pipeline.
// ---------------------------------------------------------------------------
#define BM 128
#define BN 128
#define BK 32
#define ASTR 40          // padded row length (bf16 elems), 80B: conflict-free
#define NCHUNK 24        // 3 terms * (256/32)

__global__ __launch_bounds__(256, 2) void gemm_mma_kernel(const float* __restrict__ bias) {
    __shared__ __nv_bfloat16 As[2][BM * ASTR];
    __shared__ __nv_bfloat16 Bs[2][BN * ASTR];

    const int tid  = threadIdx.x;
    const int lane = tid & 31;
    const int wid  = tid >> 5;
    const int m0   = blockIdx.y * BM;
    const int n0   = blockIdx.x * BN;
    const int wm0  = (wid >> 1) * 32;
    const int wn0  = (wid & 1) * 64;

    const int lrow = tid >> 1;            // load row 0..127 (2 threads/row)
    const int lseg = (tid & 1) * 2;       // seg pair: 2 x 16B each

    float acc[2][8][4];
    #pragma unroll
    for (int mi = 0; mi < 2; mi++)
        #pragma unroll
        for (int j = 0; j < 8; j++)
            #pragma unroll
            for (int q = 0; q < 4; q++)
                acc[mi][j][q] = 0.0f;

    // ---- async-load a chunk into buffer ----
    auto issue = [&](int c, int buf) {
        const int term = c >> 3;
        const int k0   = (c & 7) * BK;
        const __nv_bfloat16* Asrc = (term == 2) ? g_w_lo : g_w_hi;
        const __nv_bfloat16* Bsrc = (term == 1) ? g_xt_lo : g_xt_hi;
        const int p = n0 + lrow;
        const int bok = (p < NPIX) ? 16 : 0;
        const size_t poff = (size_t)(p < NPIX ? p : 0) * K_DIM + k0;
        const size_t aoff = (size_t)(m0 + lrow) * K_DIM + k0;
        #pragma unroll
        for (int s = 0; s < 2; s++) {
            int seg = lseg + s;
            cp16(smem_u32(&As[buf][lrow * ASTR + seg * 8]), Asrc + aoff + seg * 8, 16);
            cp16(smem_u32(&Bs[buf][lrow * ASTR + seg * 8]), Bsrc + poff + seg * 8, bok);
        }
    };

    issue(0, 0);
    CP_COMMIT();

    for (int c = 0; c < NCHUNK; c++) {
        if (c + 1 < NCHUNK) {
            issue(c + 1, (c + 1) & 1);
            CP_COMMIT();
            CP_WAIT(1);
        } else {
            CP_WAIT(0);
        }
        __syncthreads();

        const uint32_t aBase = smem_u32(&As[c & 1][0]);
        const uint32_t bBase = smem_u32(&Bs[c & 1][0]);

        #pragma unroll
        for (int ks = 0; ks < 2; ks++) {
            uint32_t a[2][4], b[4][4];
            #pragma unroll
            for (int mi = 0; mi < 2; mi++) {
                uint32_t addr = aBase +
                    ((wm0 + mi * 16 + (lane & 15)) * ASTR + ks * 16 + ((lane >> 4) << 3)) * 2;
                ldsm_x4(a[mi], addr);
            }
            #pragma unroll
            for (int ni = 0; ni < 4; ni++) {
                uint32_t addr = bBase +
                    ((wn0 + ni * 16 + (lane & 7) + ((lane >> 4) << 3)) * ASTR
                     + ks * 16 + ((lane >> 3) & 1) * 8) * 2;
                ldsm_x4(b[ni], addr);
            }
            #pragma unroll
            for (int mi = 0; mi < 2; mi++)
                #pragma unroll
                for (int j = 0; j < 8; j++)
                    mma16816(acc[mi][j], a[mi],
                             b[j >> 1][(j & 1) * 2], b[j >> 1][(j & 1) * 2 + 1]);
        }
        __syncthreads();
    }

    // ---- epilogue ----
    #pragma unroll
    for (int mi = 0; mi < 2; mi++) {
        const int r = m0 + wm0 + mi * 16 + (lane >> 2);
        const float b0v = bias[r];
        const float b1v = bias[r + 8];
        #pragma unroll
        for (int j = 0; j < 8; j++) {
            const int n = n0 + wn0 + j * 8 + (lane & 3) * 2;
            if (n < NPIX) {
                float2 lo = make_float2(acc[mi][j][0] + b0v, acc[mi][j][1] + b0v);
                float2 hi = make_float2(acc[mi][j][2] + b1v, acc[mi][j][3] + b1v);
                *reinterpret_cast<float2*>(&g_vel[(size_t)r * NPIX + n]) = lo;
                *reinterpret_cast<float2*>(&g_vel[(size_t)(r + 8) * NPIX + n]) = hi;
            }
        }
    }
}

// ---------------------------------------------------------------------------
// Departure point + bicubic sample (fast interior path)
// ---------------------------------------------------------------------------
__device__ __forceinline__ float cc1f(float x) {
    return (1.25f * x - 2.25f) * x * x + 1.0f;
}
__device__ __forceinline__ float cc2f(float x) {
    return ((-0.75f * x + 3.75f) * x - 6.0f) * x + 3.0f;
}

__global__ __launch_bounds__(256) void sample_kernel(
    const float* __restrict__ hf,
    const float* __restrict__ latg,
    const float* __restrict__ lng,
    const void*  __restrict__ dtp,
    float* __restrict__ out)
{
    const int p = blockIdx.x * 256 + threadIdx.x;
    const int c = blockIdx.y;
    if (p >= NPIX) return;

    const int ib = *reinterpret_cast<const int*>(dtp);
    const float dtf = (ib > -1000000 && ib < 1000000) ? (float)ib : __int_as_float(ib);

    const float u = g_vel[(size_t)c * NPIX + p];
    const float v = g_vel[(size_t)(c + C_DIM) * NPIX + p];
    const float lat_p = __ldg(&latg[p]);
    const float lon_p = __ldg(&lng[p]);

    float slp, clp, slo, clo, sla, cla;
    sincosf(-v * dtf, &slp, &clp);
    sincosf(-u * dtf, &slo, &clo);
    sincosf(lat_p,    &sla, &cla);

    float sin_lat = slp * cla + clp * clo * sla;
    const float lim = 1.0f - 1e-7f;
    sin_lat = fminf(fmaxf(sin_lat, -lim), lim);
    const float lat_dep = asinf(sin_lat);

    const float num = clp * slo;
    const float den = clp * clo * cla - slp * sla;
    const float TWO_PI = 6.28318530717958647692f;
    float lon_dep = lon_p + atan2f(num, den);
    if (lon_dep < 0.0f)     lon_dep += TWO_PI;
    if (lon_dep >= TWO_PI)  lon_dep -= TWO_PI;

    const float min_lat = __ldg(&latg[0]);
    const float max_lat = __ldg(&latg[(H_DIM - 1) * W_DIM]);
    const float min_lon = __ldg(&lng[0]);
    const float max_lon = __ldg(&lng[W_DIM - 1]);

    const float KX = 180.0f / 181.0f;
    const float KY = 90.0f / 91.0f;
    float t  = (lon_dep - min_lon) * __fdividef(1.0f, max_lon - min_lon);
    float qx = fmaf(2.0f * KX, t, 1.0f - KX);
    if (qx >= 2.0f) qx -= 2.0f;
    const float ix = qx * 180.5f;

    float s  = (lat_dep - min_lat) * __fdividef(1.0f, max_lat - min_lat);
    float gy = fmaf(2.0f * KY, s, -KY);
    if (gy < -1.0f) gy = -(2.0f + gy);
    if (gy >  1.0f) gy = 2.0f - gy;
    const float iy = (gy + 1.0f) * 90.5f;

    const float ix0f = floorf(ix);
    const float iy0f = floorf(iy);
    const float fx = ix - ix0f;
    const float fy = iy - iy0f;
    const int ix0 = (int)ix0f;
    const int iy0 = (int)iy0f;

    const float wx0 = cc2f(fx + 1.0f), wx1 = cc1f(fx),
                wx2 = cc1f(1.0f - fx), wx3 = cc2f(2.0f - fx);
    const float wy0 = cc2f(fy + 1.0f), wy1 = cc1f(fy),
                wy2 = cc1f(1.0f - fy), wy3 = cc2f(2.0f - fy);

    const float* ch = hf + (size_t)c * NPIX;
    float acc;

    if (iy0 >= 2 && iy0 <= 178 && ix0 >= 2 && ix0 <= 358) {
        const float* b0 = ch + (iy0 - 2) * W_DIM + (ix0 - 2);
        const float* b1 = b0 + W_DIM;
        const float* b2 = b1 + W_DIM;
        const float* b3 = b2 + W_DIM;
        float r0 = wx0 * __ldg(b0 + 0) + wx1 * __ldg(b0 + 1) + wx2 * __ldg(b0 + 2) + wx3 * __ldg(b0 + 3);
        float r1 = wx0 * __ldg(b1 + 0) + wx1 * __ldg(b1 + 1) + wx2 * __ldg(b1 + 2) + wx3 * __ldg(b1 + 3);
        float r2 = wx0 * __ldg(b2 + 0) + wx1 * __ldg(b2 + 1) + wx2 * __ldg(b2 + 2) + wx3 * __ldg(b2 + 3);
        float r3 = wx0 * __ldg(b3 + 0) + wx1 * __ldg(b3 + 1) + wx2 * __ldg(b3 + 2) + wx3 * __ldg(b3 + 3);
        acc = wy0 * r0 + wy1 * r1 + wy2 * r2 + wy3 * r3;
    } else {
        const float wxs[4] = {wx0, wx1, wx2, wx3};
        const float wys[4] = {wy0, wy1, wy2, wy3};
        acc = 0.f;
        #pragma unroll
        for (int i = 0; i < 4; i++) {
            int yi = iy0 + i - 1;
            yi = min(max(yi, 0), 181);
            const bool interior = (yi >= 1 && yi <= H_DIM);
            const int yy = interior ? (yi - 1) : ((yi == 0) ? 0 : (H_DIM - 1));
            const float* rowp = ch + yy * W_DIM;
            float row = 0.f;
            #pragma unroll
            for (int j = 0; j < 4; j++) {
                int xj = ix0 + j - 1;
                xj = min(max(xj, 0), 361);
                int xx;
                if (interior) {
                    xx = (xj == 0) ? (W_DIM - 1) : ((xj == 361) ? 0 : (xj - 1));
                } else {
                    xx = xj + 179;
                    if (xx >= W_DIM) xx -= W_DIM;
                }
                row += wxs[j] * __ldg(&rowp[xx]);
            }
            acc += wys[i] * row;
        }
    }

    out[(size_t)c * NPIX + p] = acc;
}

// ---------------------------------------------------------------------------
extern "C" void kernel_launch(void* const* d_in, const int* in_sizes, int n_in,
                              void* d_out, int out_size) {
    const float* hf   = (const float*)d_in[0];
    const float* latg = (const float*)d_in[1];
    const float* lng  = (const float*)d_in[2];
    const float* wv   = (const float*)d_in[3];
    const float* bv   = (const float*)d_in[4];
    const void*  dtp  = d_in[5];
    float* out = (float*)d_out;

    convert_w_kernel<<<(M_OUT * K_DIM + 255) / 256, 256>>>(wv);
    convert_x_kernel<<<NPIX / 32, 256>>>(hf);

    dim3 gg((NPIX + BN - 1) / BN, M_OUT / BM);   // 507 x 4
    gemm_mma_kernel<<<gg, 256>>>(bv);

    dim3 gs((NPIX + 255) / 256, C_DIM);
    sample_kernel<<<gs, 256>>>(hf, latg, lng, dtp, out);
}